// round 13
// baseline (speedup 1.0000x reference)
#include <cuda_runtime.h>
#include <cuda_bf16.h>
#include <cstdint>

#define NB 4
#define NN 4096
#define ND 16
#define KK 10
#define TT 12
#define SCAP 192            // per-row candidate capacity (global scratch)
#define PRE_M 2048          // prepass sample size
#define DELTA_HARD 0.1255f  // > hard bf16 screen error bound 16*2^-7 = 0.125
#define MARG 0.26f          // > 2*delta prepass margin
#define CUT_FLOOR (-0.13f)  // < -DELTA_HARD: unscreened => exact < 0
#define FULLM 0xFFFFFFFFu

typedef unsigned long long u64;

// scratch
__device__ float g_emb[NB * NN * ND];                 // fp32 embeddings
__device__ __nv_bfloat162 g_embh[NB * NN * ND / 2];   // bf16 embeddings
__device__ unsigned g_cand[(size_t)NB * NN * SCAP];   // candidate m lists
__device__ u64 g_top[NB * NN * KK];                   // exact top-10 packed
__device__ float4 g_consts[NB * NN];                  // {base, c1, vmax, -}

// ---------------------------------------------------------------------------
// f32x2 packed helpers
// ---------------------------------------------------------------------------
__device__ __forceinline__ u64 mul2(u64 a, u64 b) {
    u64 d; asm("mul.rn.f32x2 %0, %1, %2;" : "=l"(d) : "l"(a), "l"(b)); return d;
}
__device__ __forceinline__ u64 fma2(u64 a, u64 b, u64 c) {
    u64 d; asm("fma.rn.f32x2 %0, %1, %2, %3;" : "=l"(d) : "l"(a), "l"(b), "l"(c)); return d;
}
__device__ __forceinline__ float red2(u64 a) {
    unsigned lo, hi;
    asm("mov.b64 {%0, %1}, %2;" : "=r"(lo), "=r"(hi) : "l"(a));
    return __uint_as_float(lo) + __uint_as_float(hi);
}
__device__ __forceinline__ float val_of(u64 e) {
    return __uint_as_float((unsigned)(e >> 32));
}

// bf16 mma: D(16x8,f32) = A(16x16,bf16 row) * B(16x8,bf16 col) ; C = 0
__device__ __forceinline__ void mma16816(float& d0, float& d1, float& d2, float& d3,
                                         unsigned a0, unsigned a1, unsigned a2,
                                         unsigned a3, unsigned b0, unsigned b1) {
    asm volatile(
        "mma.sync.aligned.m16n8k16.row.col.f32.bf16.bf16.f32 "
        "{%0,%1,%2,%3}, {%4,%5,%6,%7}, {%8,%9}, {%10,%11,%12,%13};"
        : "=f"(d0), "=f"(d1), "=f"(d2), "=f"(d3)
        : "r"(a0), "r"(a1), "r"(a2), "r"(a3), "r"(b0), "r"(b1),
          "f"(0.f), "f"(0.f), "f"(0.f), "f"(0.f));
}

// sorted-descending inserts (caller guards)
__device__ __forceinline__ void ins10f(float* a, float v) {
#pragma unroll
    for (int i = 9; i >= 1; i--) {
        float hi = a[i - 1], lo = a[i];
        a[i] = (v > hi) ? hi : ((v > lo) ? v : lo);
    }
    if (v > a[0]) a[0] = v;
}
__device__ __forceinline__ void ins10p(u64* a, u64 p) {
#pragma unroll
    for (int i = 9; i >= 1; i--) {
        u64 hi = a[i - 1], lo = a[i];
        a[i] = (p > hi) ? hi : ((p > lo) ? p : lo);
    }
    if (p > a[0]) a[0] = p;
}

// ---------------------------------------------------------------------------
// Kernel 1: embeddings, fp32 + bf16
// ---------------------------------------------------------------------------
__global__ void emb_kernel(const float* __restrict__ x,
                           const float* __restrict__ W,
                           const float* __restrict__ bfc) {
    int i = blockIdx.x * blockDim.x + threadIdx.x;
    if (i >= NB * NN) return;
    int b = i >> 12;
    int n = i & (NN - 1);
    float xv = x[((size_t)b * TT + (TT - 1)) * NN + n];
    float4* dst = reinterpret_cast<float4*>(&g_emb[(size_t)i * ND]);
    __nv_bfloat162* dh = &g_embh[(size_t)i * (ND / 2)];
#pragma unroll
    for (int j4 = 0; j4 < 4; j4++) {
        float4 o;
        o.x = tanhf(fmaf(xv, W[j4 * 4 + 0], bfc[j4 * 4 + 0]));
        o.y = tanhf(fmaf(xv, W[j4 * 4 + 1], bfc[j4 * 4 + 1]));
        o.z = tanhf(fmaf(xv, W[j4 * 4 + 2], bfc[j4 * 4 + 2]));
        o.w = tanhf(fmaf(xv, W[j4 * 4 + 3], bfc[j4 * 4 + 3]));
        dst[j4] = o;
        dh[j4 * 2 + 0] = __floats2bfloat162_rn(o.x, o.y);
        dh[j4 * 2 + 1] = __floats2bfloat162_rn(o.z, o.w);
    }
}

// ---------------------------------------------------------------------------
// Kernel 2: HMMA screen + exact rescore. 256 thr, 128 rows/block.
// Grid (NN/128, NB) = (32, NB) = 128 blocks (single wave on 148 SMs).
// Warp w owns local rows [16w, 16w+16).
// ---------------------------------------------------------------------------
__global__ __launch_bounds__(256) void screen_kernel(const float* __restrict__ alpha_p) {
    __shared__ float smerge[128 * 40];     // prepass quad-merge scratch (20KB)
    __shared__ unsigned scnt[128];
    __shared__ float sh_cut[128];

    const int t = threadIdx.x;
    const int lane = t & 31;
    const int w = t >> 5;
    const int gid = lane >> 2;         // groupID (row within 8 / D-col group)
    const int tig = lane & 3;          // thread-in-group (k-pair / m-pair)
    const int b = blockIdx.y;
    const int n0 = blockIdx.x * 128;

    const int rowL = w * 16 + gid;     // local rows this thread filters
    const int rowH = rowL + 8;

    const unsigned* EH = reinterpret_cast<const unsigned*>(g_embh);  // bf16x2 words
    const size_t ebase = (size_t)(b * NN) * 8;   // 8 u32 per row

    // A fragments (loaded once; K=16 covered by one mma)
    const size_t aL = ebase + (size_t)(n0 + rowL) * 8;
    const size_t aH = ebase + (size_t)(n0 + rowH) * 8;
    const unsigned a0 = EH[aL + tig];
    const unsigned a1 = EH[aH + tig];
    const unsigned a2 = EH[aL + tig + 4];
    const unsigned a3 = EH[aH + tig + 4];

    // ---- prepass: approx top-10 per (thread, row) over m < PRE_M ----
    float tvL[10], tvH[10];
#pragma unroll
    for (int k = 0; k < 10; k++) { tvL[k] = 0.f; tvH[k] = 0.f; }

    for (int mb = 0; mb < PRE_M; mb += 16) {
#pragma unroll
        for (int h = 0; h < 2; h++) {
            const int mbase = mb + h * 8;
            const size_t bb = ebase + (size_t)(mbase + gid) * 8;
            unsigned b0 = EH[bb + tig];
            unsigned b1 = EH[bb + tig + 4];
            float d0, d1, d2, d3;
            mma16816(d0, d1, d2, d3, a0, a1, a2, a3, b0, b1);
            if (d0 > tvL[9]) ins10f(tvL, d0);
            if (d1 > tvL[9]) ins10f(tvL, d1);
            if (d2 > tvH[9]) ins10f(tvH, d2);
            if (d3 > tvH[9]) ins10f(tvH, d3);
        }
    }

    // quad-merge: row's 4 threads publish, one thread merges 40 -> top-10
#pragma unroll
    for (int k = 0; k < 10; k++) {
        smerge[rowL * 40 + tig * 10 + k] = tvL[k];
        smerge[rowH * 40 + tig * 10 + k] = tvH[k];
    }
    __syncthreads();
    if (t < 128) {
        float a[10];
#pragma unroll
        for (int k = 0; k < 10; k++) a[k] = smerge[t * 40 + k];
        for (int i = 10; i < 40; i++) {
            float v = smerge[t * 40 + i];
            if (v > a[9]) ins10f(a, v);
        }
        sh_cut[t] = fmaxf(a[9] - MARG, CUT_FLOOR);
        scnt[t] = 0;
    }
    __syncthreads();

    // ---- main screen: all m, frozen cut, append candidates to global ----
    const float cutL = sh_cut[rowL];
    const float cutH = sh_cut[rowH];
    unsigned* candL = g_cand + (size_t)(b * NN + n0 + rowL) * SCAP;
    unsigned* candH = g_cand + (size_t)(b * NN + n0 + rowH) * SCAP;

    for (int mb = 0; mb < NN; mb += 16) {
#pragma unroll
        for (int h = 0; h < 2; h++) {
            const int mbase = mb + h * 8;
            const size_t bb = ebase + (size_t)(mbase + gid) * 8;
            unsigned b0 = EH[bb + tig];
            unsigned b1 = EH[bb + tig + 4];
            float d0, d1, d2, d3;
            mma16816(d0, d1, d2, d3, a0, a1, a2, a3, b0, b1);
            const unsigned m0 = (unsigned)(mbase + tig * 2);
            if (d0 > cutL) {
                unsigned p = atomicAdd(&scnt[rowL], 1u);
                if (p < SCAP) candL[p] = m0;
            }
            if (d1 > cutL) {
                unsigned p = atomicAdd(&scnt[rowL], 1u);
                if (p < SCAP) candL[p] = m0 + 1;
            }
            if (d2 > cutH) {
                unsigned p = atomicAdd(&scnt[rowH], 1u);
                if (p < SCAP) candH[p] = m0;
            }
            if (d3 > cutH) {
                unsigned p = atomicAdd(&scnt[rowH], 1u);
                if (p < SCAP) candH[p] = m0 + 1;
            }
        }
    }
    __syncthreads();

    // ---- exact rescore + self-validation (thread t < 128 owns row t) ----
    if (t < 128) {
        const int rowg = b * NN + n0 + t;
        const float* embf = g_emb + (size_t)b * NN * ND;
        u64 en[8];
        {
            const u64* p = reinterpret_cast<const u64*>(g_emb + (size_t)rowg * ND);
#pragma unroll
            for (int j = 0; j < 8; j++) en[j] = p[j];
        }
        u64 top[KK];
#pragma unroll
        for (int k = 0; k < KK; k++) top[k] = 0ULL;

        const unsigned* myc = g_cand + (size_t)rowg * SCAP;
        const unsigned rawcnt = scnt[t];
        const unsigned nc = rawcnt < SCAP ? rawcnt : SCAP;
        for (unsigned i = 0; i < nc; i++) {
            unsigned m = myc[i];
            const ulonglong2* q =
                reinterpret_cast<const ulonglong2*>(embf + (size_t)m * ND);
            ulonglong2 q0 = q[0], q1 = q[1], q2 = q[2], q3 = q[3];
            u64 acc = mul2(en[0], q0.x);
            acc = fma2(en[1], q0.y, acc);
            acc = fma2(en[2], q1.x, acc);
            acc = fma2(en[3], q1.y, acc);
            acc = fma2(en[4], q2.x, acc);
            acc = fma2(en[5], q2.y, acc);
            acc = fma2(en[6], q3.x, acc);
            acc = fma2(en[7], q3.y, acc);
            float s = red2(acc);
            if (s > 0.f) {
                u64 p = ((u64)__float_as_uint(s) << 32) | (u64)m;
                if (p > top[KK - 1]) ins10p(top, p);
            }
        }

        const float cut = sh_cut[t];
        const float t9 = val_of(top[KK - 1]);
        // safe iff unscreened (exact <= cut + DELTA_HARD) cannot displace top-10
        bool ok = (rawcnt <= SCAP) &&
                  ((t9 > cut + DELTA_HARD) ||
                   (t9 == 0.f && cut <= CUT_FLOOR + 1e-6f));
        if (!ok) {
            // exact fallback: full row rescan (correctness never statistical)
#pragma unroll
            for (int k = 0; k < KK; k++) top[k] = 0ULL;
            for (unsigned m = 0; m < NN; m++) {
                const ulonglong2* q =
                    reinterpret_cast<const ulonglong2*>(embf + (size_t)m * ND);
                ulonglong2 q0 = q[0], q1 = q[1], q2 = q[2], q3 = q[3];
                u64 acc = mul2(en[0], q0.x);
                acc = fma2(en[1], q0.y, acc);
                acc = fma2(en[2], q1.x, acc);
                acc = fma2(en[3], q1.y, acc);
                acc = fma2(en[4], q2.x, acc);
                acc = fma2(en[5], q2.y, acc);
                acc = fma2(en[6], q3.x, acc);
                acc = fma2(en[7], q3.y, acc);
                float s = red2(acc);
                if (s > 0.f) {
                    u64 p = ((u64)__float_as_uint(s) << 32) | (u64)m;
                    if (p > top[KK - 1]) ins10p(top, p);
                }
            }
        }

        // softmax constants
        const float alpha = *alpha_p;
        const float a = 1.f / (1.f + expf(-alpha));
        const float oma = 1.f - a;
        float vmax = val_of(top[0]);
        float S = 0.f;
#pragma unroll
        for (int k = 0; k < KK; k++) S += expf(val_of(top[k]) - vmax);
        S += (float)(NN - KK) * expf(-vmax);
        float c1 = oma / S;
        g_consts[rowg] = make_float4(c1 * expf(-vmax), c1, vmax, 0.f);
#pragma unroll
        for (int k = 0; k < KK; k++) g_top[(size_t)rowg * KK + k] = top[k];
    }
}

// ---------------------------------------------------------------------------
// Kernel 3: out[b,row,:] = a*A_phys[row,:] + base, then top-K fix-ups.
// ---------------------------------------------------------------------------
__global__ __launch_bounds__(256) void write_kernel(
    const float* __restrict__ Aphys,
    const float* __restrict__ alpha_p,
    float* __restrict__ out) {
    const int t = threadIdx.x;
    const int b = blockIdx.x;
    const int row = blockIdx.y;

    const float alpha = *alpha_p;
    const float a = 1.f / (1.f + expf(-alpha));

    float4 c = g_consts[(size_t)b * NN + row];
    const float base = c.x, c1 = c.y, vmax = c.z;

    const float4* ap = reinterpret_cast<const float4*>(Aphys) + (size_t)row * (NN / 4);
    float4* op = reinterpret_cast<float4*>(out) + ((size_t)b * NN + row) * (NN / 4);

#pragma unroll
    for (int u = 0; u < (NN / 4) / 256; u++) {
        int i = u * 256 + t;
        float4 v = ap[i];
        float4 o;
        o.x = fmaf(a, v.x, base);
        o.y = fmaf(a, v.y, base);
        o.z = fmaf(a, v.z, base);
        o.w = fmaf(a, v.w, base);
        __stcs(&op[i], o);
    }
    __syncthreads();

    if (t < KK) {
        u64 e = g_top[((size_t)b * NN + row) * KK + t];
        if (e != 0ULL) {
            unsigned idx = (unsigned)e;
            float v = val_of(e);
            float pv = Aphys[(size_t)row * NN + idx];
            out[((size_t)b * NN + row) * NN + idx] =
                fmaf(a, pv, c1 * expf(v - vmax));
        }
    }
}

// ---------------------------------------------------------------------------
extern "C" void kernel_launch(void* const* d_in, const int* in_sizes, int n_in,
                              void* d_out, int out_size) {
    const float* x     = (const float*)d_in[0];
    const float* Aphys = (const float*)d_in[1];
    const float* Wfc   = (const float*)d_in[2];
    const float* bfc   = (const float*)d_in[3];
    const float* alpha = (const float*)d_in[4];
    float* out = (float*)d_out;

    emb_kernel<<<(NB * NN + 255) / 256, 256>>>(x, Wfc, bfc);
    dim3 grid2(NN / 128, NB);
    screen_kernel<<<grid2, 256>>>(alpha);
    dim3 grid3(NB, NN);
    write_kernel<<<grid3, 256>>>(Aphys, alpha, out);
}

// round 14
// speedup vs baseline: 2.1011x; 2.1011x over previous
#include <cuda_runtime.h>
#include <cstdint>

#define NB 4
#define NN 4096
#define ND 16
#define KK 10
#define TT 12
#define SCAP 1024           // per-row candidate capacity (global scratch)
#define DHARD 0.018f        // > tf32 screen error bound 16*2^-10 + accum slack
#define CUTMARG 0.037f      // > 2*DHARD
#define CUTFLOOR (-0.02f)   // <= -DHARD: below floor => exact < 0
#define FULLM 0xFFFFFFFFu

typedef unsigned long long u64;

// scratch
__device__ float g_emb[NB * NN * ND];                 // fp32 embeddings
__device__ unsigned g_embt[NB * NN * ND];             // tf32 embeddings (bits)
__device__ unsigned g_cand[(size_t)NB * NN * SCAP];   // candidate m lists
__device__ u64 g_top[NB * NN * KK];                   // exact top-10 packed
__device__ float4 g_consts[NB * NN];                  // {base, c1, vmax, -}

// ---------------------------------------------------------------------------
// f32x2 packed helpers
// ---------------------------------------------------------------------------
__device__ __forceinline__ u64 mul2(u64 a, u64 b) {
    u64 d; asm("mul.rn.f32x2 %0, %1, %2;" : "=l"(d) : "l"(a), "l"(b)); return d;
}
__device__ __forceinline__ u64 fma2(u64 a, u64 b, u64 c) {
    u64 d; asm("fma.rn.f32x2 %0, %1, %2, %3;" : "=l"(d) : "l"(a), "l"(b), "l"(c)); return d;
}
__device__ __forceinline__ float red2(u64 a) {
    unsigned lo, hi;
    asm("mov.b64 {%0, %1}, %2;" : "=r"(lo), "=r"(hi) : "l"(a));
    return __uint_as_float(lo) + __uint_as_float(hi);
}
__device__ __forceinline__ float val_of(u64 e) {
    return __uint_as_float((unsigned)(e >> 32));
}

// tf32 mma m16n8k8: D(16x8 f32) += A(16x8 tf32 row) * B(8x8 tf32 col)
__device__ __forceinline__ void mma_tf32(float& d0, float& d1, float& d2, float& d3,
                                         unsigned a0, unsigned a1, unsigned a2,
                                         unsigned a3, unsigned b0, unsigned b1,
                                         float c0, float c1, float c2, float c3) {
    asm volatile(
        "mma.sync.aligned.m16n8k8.row.col.f32.tf32.tf32.f32 "
        "{%0,%1,%2,%3}, {%4,%5,%6,%7}, {%8,%9}, {%10,%11,%12,%13};"
        : "=f"(d0), "=f"(d1), "=f"(d2), "=f"(d3)
        : "r"(a0), "r"(a1), "r"(a2), "r"(a3), "r"(b0), "r"(b1),
          "f"(c0), "f"(c1), "f"(c2), "f"(c3));
}

// sorted-descending inserts (caller guards)
__device__ __forceinline__ void ins10f(float* a, float v) {
#pragma unroll
    for (int i = 9; i >= 1; i--) {
        float hi = a[i - 1], lo = a[i];
        a[i] = (v > hi) ? hi : ((v > lo) ? v : lo);
    }
    if (v > a[0]) a[0] = v;
}
__device__ __forceinline__ void ins10p(u64* a, u64 p) {
#pragma unroll
    for (int i = 9; i >= 1; i--) {
        u64 hi = a[i - 1], lo = a[i];
        a[i] = (p > hi) ? hi : ((p > lo) ? p : lo);
    }
    if (p > a[0]) a[0] = p;
}

// exact fp32 dot of row-embedding regs en[8] with emb row m
__device__ __forceinline__ float exact_dot(const u64* en, const float* embf,
                                           unsigned m) {
    const ulonglong2* q = reinterpret_cast<const ulonglong2*>(embf + (size_t)m * ND);
    ulonglong2 q0 = q[0], q1 = q[1], q2 = q[2], q3 = q[3];
    u64 acc = mul2(en[0], q0.x);
    acc = fma2(en[1], q0.y, acc);
    acc = fma2(en[2], q1.x, acc);
    acc = fma2(en[3], q1.y, acc);
    acc = fma2(en[4], q2.x, acc);
    acc = fma2(en[5], q2.y, acc);
    acc = fma2(en[6], q3.x, acc);
    acc = fma2(en[7], q3.y, acc);
    return red2(acc);
}

// ---------------------------------------------------------------------------
// Kernel 1: embeddings, fp32 + tf32 copy
// ---------------------------------------------------------------------------
__global__ void emb_kernel(const float* __restrict__ x,
                           const float* __restrict__ W,
                           const float* __restrict__ bfc) {
    int i = blockIdx.x * blockDim.x + threadIdx.x;
    if (i >= NB * NN) return;
    int b = i >> 12;
    int n = i & (NN - 1);
    float xv = x[((size_t)b * TT + (TT - 1)) * NN + n];
    float4* dst = reinterpret_cast<float4*>(&g_emb[(size_t)i * ND]);
    uint4* dt = reinterpret_cast<uint4*>(&g_embt[(size_t)i * ND]);
#pragma unroll
    for (int j4 = 0; j4 < 4; j4++) {
        float4 o;
        o.x = tanhf(fmaf(xv, W[j4 * 4 + 0], bfc[j4 * 4 + 0]));
        o.y = tanhf(fmaf(xv, W[j4 * 4 + 1], bfc[j4 * 4 + 1]));
        o.z = tanhf(fmaf(xv, W[j4 * 4 + 2], bfc[j4 * 4 + 2]));
        o.w = tanhf(fmaf(xv, W[j4 * 4 + 3], bfc[j4 * 4 + 3]));
        dst[j4] = o;
        uint4 tv;
        asm("cvt.rna.tf32.f32 %0, %1;" : "=r"(tv.x) : "f"(o.x));
        asm("cvt.rna.tf32.f32 %0, %1;" : "=r"(tv.y) : "f"(o.y));
        asm("cvt.rna.tf32.f32 %0, %1;" : "=r"(tv.z) : "f"(o.z));
        asm("cvt.rna.tf32.f32 %0, %1;" : "=r"(tv.w) : "f"(o.w));
        dt[j4] = tv;
    }
}

// ---------------------------------------------------------------------------
// Kernel 2: TF32 MMA screen (2 passes) + quad-parallel exact rescore.
// 256 thr, 128 rows/block. Grid (NN/128, NB) = 128 blocks.
// Warp w owns local rows [16w, 16w+16): thread quad (gid) handles
// rowL = 16w+gid, rowH = rowL+8 (mma m16n8k8 fragment layout).
// ---------------------------------------------------------------------------
__global__ __launch_bounds__(256) void screen_kernel(const float* __restrict__ alpha_p) {
    __shared__ u64 smbuf[128 * 40];       // 40KB: merge scratch (f32 or u64)
    __shared__ unsigned scnt[128];
    __shared__ float sh_cut[128];

    const int t = threadIdx.x;
    const int lane = t & 31;
    const int w = t >> 5;
    const int gid = lane >> 2;         // groupID (0..7)
    const int tig = lane & 3;          // thread-in-group (0..3)
    const int b = blockIdx.y;
    const int n0 = blockIdx.x * 128;

    const int rowL = w * 16 + gid;
    const int rowH = rowL + 8;

    const unsigned* ET = g_embt + (size_t)(b * NN) * ND;

    // A fragments for both k-halves (fixed across the m loop)
    unsigned aL0 = ET[(size_t)(n0 + rowL) * ND + tig];
    unsigned aH0 = ET[(size_t)(n0 + rowH) * ND + tig];
    unsigned aL1 = ET[(size_t)(n0 + rowL) * ND + tig + 4];
    unsigned aH1 = ET[(size_t)(n0 + rowH) * ND + tig + 4];
    unsigned aL2 = ET[(size_t)(n0 + rowL) * ND + tig + 8];
    unsigned aH2 = ET[(size_t)(n0 + rowH) * ND + tig + 8];
    unsigned aL3 = ET[(size_t)(n0 + rowL) * ND + tig + 12];
    unsigned aH3 = ET[(size_t)(n0 + rowH) * ND + tig + 12];

    // ---- pass 1: approx top-10 per (thread,row) over all m ----
    float tvL[10], tvH[10];
#pragma unroll
    for (int k = 0; k < 10; k++) { tvL[k] = -1e30f; tvH[k] = -1e30f; }

    for (int mb = 0; mb < NN; mb += 8) {
        const size_t bbase = (size_t)(mb + gid) * ND;
        unsigned b00 = ET[bbase + tig];
        unsigned b01 = ET[bbase + tig + 4];
        unsigned b10 = ET[bbase + tig + 8];
        unsigned b11 = ET[bbase + tig + 12];
        float d0, d1, d2, d3;
        mma_tf32(d0, d1, d2, d3, aL0, aH0, aL1, aH1, b00, b01,
                 0.f, 0.f, 0.f, 0.f);
        mma_tf32(d0, d1, d2, d3, aL2, aH2, aL3, aH3, b10, b11,
                 d0, d1, d2, d3);
        if (d0 > tvL[9]) ins10f(tvL, d0);
        if (d1 > tvL[9]) ins10f(tvL, d1);
        if (d2 > tvH[9]) ins10f(tvH, d2);
        if (d3 > tvH[9]) ins10f(tvH, d3);
    }

    // quad merge -> cut per row
    float* fm = reinterpret_cast<float*>(smbuf);
#pragma unroll
    for (int k = 0; k < 10; k++) {
        fm[rowL * 40 + tig * 10 + k] = tvL[k];
        fm[rowH * 40 + tig * 10 + k] = tvH[k];
    }
    __syncthreads();
    if (t < 128) {
        float a[10];
#pragma unroll
        for (int k = 0; k < 10; k++) a[k] = fm[t * 40 + k];
        for (int i = 10; i < 40; i++) {
            float v = fm[t * 40 + i];
            if (v > a[9]) ins10f(a, v);
        }
        sh_cut[t] = fmaxf(a[9] - CUTMARG, CUTFLOOR);
        scnt[t] = 0;
    }
    __syncthreads();

    // ---- pass 2: append candidates (approx > cut) to global lists ----
    const float cutL = sh_cut[rowL];
    const float cutH = sh_cut[rowH];
    unsigned* candL = g_cand + (size_t)(b * NN + n0 + rowL) * SCAP;
    unsigned* candH = g_cand + (size_t)(b * NN + n0 + rowH) * SCAP;

    for (int mb = 0; mb < NN; mb += 8) {
        const size_t bbase = (size_t)(mb + gid) * ND;
        unsigned b00 = ET[bbase + tig];
        unsigned b01 = ET[bbase + tig + 4];
        unsigned b10 = ET[bbase + tig + 8];
        unsigned b11 = ET[bbase + tig + 12];
        float d0, d1, d2, d3;
        mma_tf32(d0, d1, d2, d3, aL0, aH0, aL1, aH1, b00, b01,
                 0.f, 0.f, 0.f, 0.f);
        mma_tf32(d0, d1, d2, d3, aL2, aH2, aL3, aH3, b10, b11,
                 d0, d1, d2, d3);
        const unsigned m0 = (unsigned)(mb + tig * 2);
        if (d0 > cutL) {
            unsigned p = atomicAdd(&scnt[rowL], 1u);
            if (p < SCAP) candL[p] = m0;
        }
        if (d1 > cutL) {
            unsigned p = atomicAdd(&scnt[rowL], 1u);
            if (p < SCAP) candL[p] = m0 + 1;
        }
        if (d2 > cutH) {
            unsigned p = atomicAdd(&scnt[rowH], 1u);
            if (p < SCAP) candH[p] = m0;
        }
        if (d3 > cutH) {
            unsigned p = atomicAdd(&scnt[rowH], 1u);
            if (p < SCAP) candH[p] = m0 + 1;
        }
    }
    __syncthreads();

    // ---- quad-parallel exact rescore: thread handles its 2 rows, stride 4 ----
    const float* embf = g_emb + (size_t)b * NN * ND;
#pragma unroll
    for (int half = 0; half < 2; half++) {
        const int row = (half == 0) ? rowL : rowH;
        const int rowg = b * NN + n0 + row;
        u64 en[8];
        {
            const u64* p = reinterpret_cast<const u64*>(g_emb + (size_t)rowg * ND);
#pragma unroll
            for (int j = 0; j < 8; j++) en[j] = p[j];
        }
        u64 top[KK];
#pragma unroll
        for (int k = 0; k < KK; k++) top[k] = 0ULL;

        const unsigned* myc = g_cand + (size_t)rowg * SCAP;
        const unsigned rawcnt = scnt[row];
        const unsigned nc = rawcnt < SCAP ? rawcnt : SCAP;
        for (unsigned i = tig; i < nc; i += 4) {
            unsigned m = myc[i];
            float s = exact_dot(en, embf, m);
            if (s > 0.f) {
                u64 p = ((u64)__float_as_uint(s) << 32) | (u64)m;
                if (p > top[KK - 1]) ins10p(top, p);
            }
        }
#pragma unroll
        for (int k = 0; k < KK; k++) smbuf[row * 40 + tig * 10 + k] = top[k];
    }
    __syncthreads();

    // ---- final merge + consts (thread t < 128 owns row t) ----
    if (t < 128) {
        const int rowg = b * NN + n0 + t;
        u64 top[KK];
#pragma unroll
        for (int k = 0; k < KK; k++) top[k] = smbuf[t * 40 + k];
        for (int i = 10; i < 40; i++) {
            u64 p = smbuf[t * 40 + i];
            if (p > top[KK - 1]) ins10p(top, p);
        }

        if (scnt[t] > SCAP) {
            // overflow fallback (safety net; expected never with SCAP=1024)
            u64 en[8];
            const u64* pp = reinterpret_cast<const u64*>(g_emb + (size_t)rowg * ND);
#pragma unroll
            for (int j = 0; j < 8; j++) en[j] = pp[j];
#pragma unroll
            for (int k = 0; k < KK; k++) top[k] = 0ULL;
            for (unsigned m = 0; m < NN; m++) {
                float s = exact_dot(en, embf, m);
                if (s > 0.f) {
                    u64 p = ((u64)__float_as_uint(s) << 32) | (u64)m;
                    if (p > top[KK - 1]) ins10p(top, p);
                }
            }
        }

        const float alpha = *alpha_p;
        const float a = 1.f / (1.f + expf(-alpha));
        const float oma = 1.f - a;
        float vmax = val_of(top[0]);
        float S = 0.f;
#pragma unroll
        for (int k = 0; k < KK; k++) S += expf(val_of(top[k]) - vmax);
        S += (float)(NN - KK) * expf(-vmax);
        float c1 = oma / S;
        g_consts[rowg] = make_float4(c1 * expf(-vmax), c1, vmax, 0.f);
#pragma unroll
        for (int k = 0; k < KK; k++) g_top[(size_t)rowg * KK + k] = top[k];
    }
}

// ---------------------------------------------------------------------------
// Kernel 3: out[b,row,:] = a*A_phys[row,:] + base, then top-K fix-ups.
// ---------------------------------------------------------------------------
__global__ __launch_bounds__(256) void write_kernel(
    const float* __restrict__ Aphys,
    const float* __restrict__ alpha_p,
    float* __restrict__ out) {
    const int t = threadIdx.x;
    const int b = blockIdx.x;
    const int row = blockIdx.y;

    const float alpha = *alpha_p;
    const float a = 1.f / (1.f + expf(-alpha));

    float4 c = g_consts[(size_t)b * NN + row];
    const float base = c.x, c1 = c.y, vmax = c.z;

    const float4* ap = reinterpret_cast<const float4*>(Aphys) + (size_t)row * (NN / 4);
    float4* op = reinterpret_cast<float4*>(out) + ((size_t)b * NN + row) * (NN / 4);

#pragma unroll
    for (int u = 0; u < (NN / 4) / 256; u++) {
        int i = u * 256 + t;
        float4 v = ap[i];
        float4 o;
        o.x = fmaf(a, v.x, base);
        o.y = fmaf(a, v.y, base);
        o.z = fmaf(a, v.z, base);
        o.w = fmaf(a, v.w, base);
        __stcs(&op[i], o);
    }
    __syncthreads();

    if (t < KK) {
        u64 e = g_top[((size_t)b * NN + row) * KK + t];
        if (e != 0ULL) {
            unsigned idx = (unsigned)e;
            float v = val_of(e);
            float pv = Aphys[(size_t)row * NN + idx];
            out[((size_t)b * NN + row) * NN + idx] =
                fmaf(a, pv, c1 * expf(v - vmax));
        }
    }
}

// ---------------------------------------------------------------------------
extern "C" void kernel_launch(void* const* d_in, const int* in_sizes, int n_in,
                              void* d_out, int out_size) {
    const float* x     = (const float*)d_in[0];
    const float* Aphys = (const float*)d_in[1];
    const float* Wfc   = (const float*)d_in[2];
    const float* bfc   = (const float*)d_in[3];
    const float* alpha = (const float*)d_in[4];
    float* out = (float*)d_out;

    emb_kernel<<<(NB * NN + 255) / 256, 256>>>(x, Wfc, bfc);
    dim3 grid2(NN / 128, NB);
    screen_kernel<<<grid2, 256>>>(alpha);
    dim3 grid3(NB, NN);
    write_kernel<<<grid3, 256>>>(Aphys, alpha, out);
}

// round 15
// speedup vs baseline: 2.1644x; 1.0301x over previous
#include <cuda_runtime.h>
#include <cstdint>

#define NB 4
#define NN 4096
#define ND 16
#define KK 10
#define TT 12
#define SCAP 1024           // per-row candidate capacity (global scratch)
#define DHARD 0.018f        // > tf32 screen error bound 16*2^-10 + accum slack
#define CUTMARG 0.037f      // > 2*DHARD
#define CUTFLOOR (-0.02f)   // <= -DHARD: below floor => exact < 0
#define FULLM 0xFFFFFFFFu

typedef unsigned long long u64;

// scratch
__device__ float g_emb[NB * NN * ND];                 // fp32 embeddings
__device__ unsigned g_embt[NB * NN * ND];             // tf32 embeddings (bits)
__device__ unsigned g_cand[(size_t)NB * NN * SCAP];   // candidate m lists
__device__ u64 g_top[NB * NN * KK];                   // exact top-10 packed
__device__ float4 g_consts[NB * NN];                  // {base, c1, vmax, -}

// ---------------------------------------------------------------------------
// f32x2 packed helpers
// ---------------------------------------------------------------------------
__device__ __forceinline__ u64 mul2(u64 a, u64 b) {
    u64 d; asm("mul.rn.f32x2 %0, %1, %2;" : "=l"(d) : "l"(a), "l"(b)); return d;
}
__device__ __forceinline__ u64 fma2(u64 a, u64 b, u64 c) {
    u64 d; asm("fma.rn.f32x2 %0, %1, %2, %3;" : "=l"(d) : "l"(a), "l"(b), "l"(c)); return d;
}
__device__ __forceinline__ float red2(u64 a) {
    unsigned lo, hi;
    asm("mov.b64 {%0, %1}, %2;" : "=r"(lo), "=r"(hi) : "l"(a));
    return __uint_as_float(lo) + __uint_as_float(hi);
}
__device__ __forceinline__ float val_of(u64 e) {
    return __uint_as_float((unsigned)(e >> 32));
}

// tf32 mma m16n8k8: D(16x8 f32) += A(16x8 tf32 row) * B(8x8 tf32 col)
__device__ __forceinline__ void mma_tf32(float& d0, float& d1, float& d2, float& d3,
                                         unsigned a0, unsigned a1, unsigned a2,
                                         unsigned a3, unsigned b0, unsigned b1,
                                         float c0, float c1, float c2, float c3) {
    asm volatile(
        "mma.sync.aligned.m16n8k8.row.col.f32.tf32.tf32.f32 "
        "{%0,%1,%2,%3}, {%4,%5,%6,%7}, {%8,%9}, {%10,%11,%12,%13};"
        : "=f"(d0), "=f"(d1), "=f"(d2), "=f"(d3)
        : "r"(a0), "r"(a1), "r"(a2), "r"(a3), "r"(b0), "r"(b1),
          "f"(c0), "f"(c1), "f"(c2), "f"(c3));
}

// sorted-descending inserts (caller guards)
__device__ __forceinline__ void ins10f(float* a, float v) {
#pragma unroll
    for (int i = 9; i >= 1; i--) {
        float hi = a[i - 1], lo = a[i];
        a[i] = (v > hi) ? hi : ((v > lo) ? v : lo);
    }
    if (v > a[0]) a[0] = v;
}
__device__ __forceinline__ void ins10p(u64* a, u64 p) {
#pragma unroll
    for (int i = 9; i >= 1; i--) {
        u64 hi = a[i - 1], lo = a[i];
        a[i] = (p > hi) ? hi : ((p > lo) ? p : lo);
    }
    if (p > a[0]) a[0] = p;
}

// exact fp32 dot of row-embedding regs en[8] with emb row m
__device__ __forceinline__ float exact_dot(const u64* en, const float* embf,
                                           unsigned m) {
    const ulonglong2* q = reinterpret_cast<const ulonglong2*>(embf + (size_t)m * ND);
    ulonglong2 q0 = q[0], q1 = q[1], q2 = q[2], q3 = q[3];
    u64 acc = mul2(en[0], q0.x);
    acc = fma2(en[1], q0.y, acc);
    acc = fma2(en[2], q1.x, acc);
    acc = fma2(en[3], q1.y, acc);
    acc = fma2(en[4], q2.x, acc);
    acc = fma2(en[5], q2.y, acc);
    acc = fma2(en[6], q3.x, acc);
    acc = fma2(en[7], q3.y, acc);
    return red2(acc);
}

// ---------------------------------------------------------------------------
// Kernel 1: embeddings, fp32 + tf32 copy
// ---------------------------------------------------------------------------
__global__ void emb_kernel(const float* __restrict__ x,
                           const float* __restrict__ W,
                           const float* __restrict__ bfc) {
    int i = blockIdx.x * blockDim.x + threadIdx.x;
    if (i >= NB * NN) return;
    int b = i >> 12;
    int n = i & (NN - 1);
    float xv = x[((size_t)b * TT + (TT - 1)) * NN + n];
    float4* dst = reinterpret_cast<float4*>(&g_emb[(size_t)i * ND]);
    uint4* dt = reinterpret_cast<uint4*>(&g_embt[(size_t)i * ND]);
#pragma unroll
    for (int j4 = 0; j4 < 4; j4++) {
        float4 o;
        o.x = tanhf(fmaf(xv, W[j4 * 4 + 0], bfc[j4 * 4 + 0]));
        o.y = tanhf(fmaf(xv, W[j4 * 4 + 1], bfc[j4 * 4 + 1]));
        o.z = tanhf(fmaf(xv, W[j4 * 4 + 2], bfc[j4 * 4 + 2]));
        o.w = tanhf(fmaf(xv, W[j4 * 4 + 3], bfc[j4 * 4 + 3]));
        dst[j4] = o;
        uint4 tv;
        asm("cvt.rna.tf32.f32 %0, %1;" : "=r"(tv.x) : "f"(o.x));
        asm("cvt.rna.tf32.f32 %0, %1;" : "=r"(tv.y) : "f"(o.y));
        asm("cvt.rna.tf32.f32 %0, %1;" : "=r"(tv.z) : "f"(o.z));
        asm("cvt.rna.tf32.f32 %0, %1;" : "=r"(tv.w) : "f"(o.w));
        dt[j4] = tv;
    }
}

// ---------------------------------------------------------------------------
// Kernel 2: TF32 MMA screen (2 passes) + quad-parallel exact rescore.
// 256 thr, 128 rows/block. Grid (NN/128, NB) = 128 blocks.
// Warp w owns local rows [16w, 16w+16): thread quad (gid) handles
// rowL = 16w+gid, rowH = rowL+8 (mma m16n8k8 fragment layout).
// ---------------------------------------------------------------------------
__global__ __launch_bounds__(256) void screen_kernel(const float* __restrict__ alpha_p) {
    __shared__ u64 smbuf[128 * 40];       // 40KB: merge scratch (f32 or u64)
    __shared__ unsigned scnt[128];
    __shared__ float sh_cut[128];

    const int t = threadIdx.x;
    const int lane = t & 31;
    const int w = t >> 5;
    const int gid = lane >> 2;         // groupID (0..7)
    const int tig = lane & 3;          // thread-in-group (0..3)
    const int b = blockIdx.y;
    const int n0 = blockIdx.x * 128;

    const int rowL = w * 16 + gid;
    const int rowH = rowL + 8;

    const unsigned* ET = g_embt + (size_t)(b * NN) * ND;

    // A fragments for both k-halves (fixed across the m loop)
    unsigned aL0 = ET[(size_t)(n0 + rowL) * ND + tig];
    unsigned aH0 = ET[(size_t)(n0 + rowH) * ND + tig];
    unsigned aL1 = ET[(size_t)(n0 + rowL) * ND + tig + 4];
    unsigned aH1 = ET[(size_t)(n0 + rowH) * ND + tig + 4];
    unsigned aL2 = ET[(size_t)(n0 + rowL) * ND + tig + 8];
    unsigned aH2 = ET[(size_t)(n0 + rowH) * ND + tig + 8];
    unsigned aL3 = ET[(size_t)(n0 + rowL) * ND + tig + 12];
    unsigned aH3 = ET[(size_t)(n0 + rowH) * ND + tig + 12];

    // ---- pass 1: approx top-10 per (thread,row) over all m ----
    float tvL[10], tvH[10];
#pragma unroll
    for (int k = 0; k < 10; k++) { tvL[k] = -1e30f; tvH[k] = -1e30f; }

    for (int mb = 0; mb < NN; mb += 8) {
        const size_t bbase = (size_t)(mb + gid) * ND;
        unsigned b00 = ET[bbase + tig];
        unsigned b01 = ET[bbase + tig + 4];
        unsigned b10 = ET[bbase + tig + 8];
        unsigned b11 = ET[bbase + tig + 12];
        float d0, d1, d2, d3;
        mma_tf32(d0, d1, d2, d3, aL0, aH0, aL1, aH1, b00, b01,
                 0.f, 0.f, 0.f, 0.f);
        mma_tf32(d0, d1, d2, d3, aL2, aH2, aL3, aH3, b10, b11,
                 d0, d1, d2, d3);
        if (d0 > tvL[9]) ins10f(tvL, d0);
        if (d1 > tvL[9]) ins10f(tvL, d1);
        if (d2 > tvH[9]) ins10f(tvH, d2);
        if (d3 > tvH[9]) ins10f(tvH, d3);
    }

    // quad merge -> cut per row
    float* fm = reinterpret_cast<float*>(smbuf);
#pragma unroll
    for (int k = 0; k < 10; k++) {
        fm[rowL * 40 + tig * 10 + k] = tvL[k];
        fm[rowH * 40 + tig * 10 + k] = tvH[k];
    }
    __syncthreads();
    if (t < 128) {
        float a[10];
#pragma unroll
        for (int k = 0; k < 10; k++) a[k] = fm[t * 40 + k];
        for (int i = 10; i < 40; i++) {
            float v = fm[t * 40 + i];
            if (v > a[9]) ins10f(a, v);
        }
        sh_cut[t] = fmaxf(a[9] - CUTMARG, CUTFLOOR);
        scnt[t] = 0;
    }
    __syncthreads();

    // ---- pass 2: append candidates (approx > cut) to global lists ----
    const float cutL = sh_cut[rowL];
    const float cutH = sh_cut[rowH];
    unsigned* candL = g_cand + (size_t)(b * NN + n0 + rowL) * SCAP;
    unsigned* candH = g_cand + (size_t)(b * NN + n0 + rowH) * SCAP;

    for (int mb = 0; mb < NN; mb += 8) {
        const size_t bbase = (size_t)(mb + gid) * ND;
        unsigned b00 = ET[bbase + tig];
        unsigned b01 = ET[bbase + tig + 4];
        unsigned b10 = ET[bbase + tig + 8];
        unsigned b11 = ET[bbase + tig + 12];
        float d0, d1, d2, d3;
        mma_tf32(d0, d1, d2, d3, aL0, aH0, aL1, aH1, b00, b01,
                 0.f, 0.f, 0.f, 0.f);
        mma_tf32(d0, d1, d2, d3, aL2, aH2, aL3, aH3, b10, b11,
                 d0, d1, d2, d3);
        const unsigned m0 = (unsigned)(mb + tig * 2);
        if (d0 > cutL) {
            unsigned p = atomicAdd(&scnt[rowL], 1u);
            if (p < SCAP) candL[p] = m0;
        }
        if (d1 > cutL) {
            unsigned p = atomicAdd(&scnt[rowL], 1u);
            if (p < SCAP) candL[p] = m0 + 1;
        }
        if (d2 > cutH) {
            unsigned p = atomicAdd(&scnt[rowH], 1u);
            if (p < SCAP) candH[p] = m0;
        }
        if (d3 > cutH) {
            unsigned p = atomicAdd(&scnt[rowH], 1u);
            if (p < SCAP) candH[p] = m0 + 1;
        }
    }
    __syncthreads();

    // ---- quad-parallel exact rescore: thread handles its 2 rows, stride 4 ----
    const float* embf = g_emb + (size_t)b * NN * ND;
#pragma unroll
    for (int half = 0; half < 2; half++) {
        const int row = (half == 0) ? rowL : rowH;
        const int rowg = b * NN + n0 + row;
        u64 en[8];
        {
            const u64* p = reinterpret_cast<const u64*>(g_emb + (size_t)rowg * ND);
#pragma unroll
            for (int j = 0; j < 8; j++) en[j] = p[j];
        }
        u64 top[KK];
#pragma unroll
        for (int k = 0; k < KK; k++) top[k] = 0ULL;

        const unsigned* myc = g_cand + (size_t)rowg * SCAP;
        const unsigned rawcnt = scnt[row];
        const unsigned nc = rawcnt < SCAP ? rawcnt : SCAP;
        for (unsigned i = tig; i < nc; i += 4) {
            unsigned m = myc[i];
            float s = exact_dot(en, embf, m);
            if (s > 0.f) {
                u64 p = ((u64)__float_as_uint(s) << 32) | (u64)m;
                if (p > top[KK - 1]) ins10p(top, p);
            }
        }
#pragma unroll
        for (int k = 0; k < KK; k++) smbuf[row * 40 + tig * 10 + k] = top[k];
    }
    __syncthreads();

    // ---- final merge + consts (thread t < 128 owns row t) ----
    if (t < 128) {
        const int rowg = b * NN + n0 + t;
        u64 top[KK];
#pragma unroll
        for (int k = 0; k < KK; k++) top[k] = smbuf[t * 40 + k];
        for (int i = 10; i < 40; i++) {
            u64 p = smbuf[t * 40 + i];
            if (p > top[KK - 1]) ins10p(top, p);
        }

        if (scnt[t] > SCAP) {
            // overflow fallback (safety net; expected never with SCAP=1024)
            u64 en[8];
            const u64* pp = reinterpret_cast<const u64*>(g_emb + (size_t)rowg * ND);
#pragma unroll
            for (int j = 0; j < 8; j++) en[j] = pp[j];
#pragma unroll
            for (int k = 0; k < KK; k++) top[k] = 0ULL;
            for (unsigned m = 0; m < NN; m++) {
                float s = exact_dot(en, embf, m);
                if (s > 0.f) {
                    u64 p = ((u64)__float_as_uint(s) << 32) | (u64)m;
                    if (p > top[KK - 1]) ins10p(top, p);
                }
            }
        }

        const float alpha = *alpha_p;
        const float a = 1.f / (1.f + expf(-alpha));
        const float oma = 1.f - a;
        float vmax = val_of(top[0]);
        float S = 0.f;
#pragma unroll
        for (int k = 0; k < KK; k++) S += expf(val_of(top[k]) - vmax);
        S += (float)(NN - KK) * expf(-vmax);
        float c1 = oma / S;
        g_consts[rowg] = make_float4(c1 * expf(-vmax), c1, vmax, 0.f);
#pragma unroll
        for (int k = 0; k < KK; k++) g_top[(size_t)rowg * KK + k] = top[k];
    }
}

// ---------------------------------------------------------------------------
// Kernel 3: out[b,row,:] = a*A_phys[row,:] + base, then top-K fix-ups.
// ---------------------------------------------------------------------------
__global__ __launch_bounds__(256) void write_kernel(
    const float* __restrict__ Aphys,
    const float* __restrict__ alpha_p,
    float* __restrict__ out) {
    const int t = threadIdx.x;
    const int b = blockIdx.x;
    const int row = blockIdx.y;

    const float alpha = *alpha_p;
    const float a = 1.f / (1.f + expf(-alpha));

    float4 c = g_consts[(size_t)b * NN + row];
    const float base = c.x, c1 = c.y, vmax = c.z;

    const float4* ap = reinterpret_cast<const float4*>(Aphys) + (size_t)row * (NN / 4);
    float4* op = reinterpret_cast<float4*>(out) + ((size_t)b * NN + row) * (NN / 4);

#pragma unroll
    for (int u = 0; u < (NN / 4) / 256; u++) {
        int i = u * 256 + t;
        float4 v = ap[i];
        float4 o;
        o.x = fmaf(a, v.x, base);
        o.y = fmaf(a, v.y, base);
        o.z = fmaf(a, v.z, base);
        o.w = fmaf(a, v.w, base);
        __stcs(&op[i], o);
    }
    __syncthreads();

    if (t < KK) {
        u64 e = g_top[((size_t)b * NN + row) * KK + t];
        if (e != 0ULL) {
            unsigned idx = (unsigned)e;
            float v = val_of(e);
            float pv = Aphys[(size_t)row * NN + idx];
            out[((size_t)b * NN + row) * NN + idx] =
                fmaf(a, pv, c1 * expf(v - vmax));
        }
    }
}

// ---------------------------------------------------------------------------
extern "C" void kernel_launch(void* const* d_in, const int* in_sizes, int n_in,
                              void* d_out, int out_size) {
    const float* x     = (const float*)d_in[0];
    const float* Aphys = (const float*)d_in[1];
    const float* Wfc   = (const float*)d_in[2];
    const float* bfc   = (const float*)d_in[3];
    const float* alpha = (const float*)d_in[4];
    float* out = (float*)d_out;

    emb_kernel<<<(NB * NN + 255) / 256, 256>>>(x, Wfc, bfc);
    dim3 grid2(NN / 128, NB);
    screen_kernel<<<grid2, 256>>>(alpha);
    dim3 grid3(NB, NN);
    write_kernel<<<grid3, 256>>>(Aphys, alpha, out);
}